// round 9
// baseline (speedup 1.0000x reference)
#include <cuda_runtime.h>
#include <cuda_fp16.h>
#include <cstdint>

// ---------------------------------------------------------------------------
// CompressedLinear: y = ((x @ Vh^T) * S) @ U^T + bias
// mma.sync fp16 path. R8 ncu: tensor=56%, occ=12.3% -> still only 8 warps/SM
// (2/SMSP); LDS+pipeline-wait latency unhidden. This round: 256 thr/CTA,
// 8 warps @ 32x64 warp tile (4x2 grid), 2 CTAs/SM => 16 warps/SM (4/SMSP).
// Smem both paths exactly 110592 B. Fused launch + per-M-block flags kept.
// ---------------------------------------------------------------------------

#define M_TOK   8192
#define IN_F    4096
#define OUT_F   4096
#define RANK    1024

#define TM      128
#define TN      128
#define G1_TN_TILES (RANK / TN)                    // 8
#define G1_TILES    ((M_TOK / TM) * G1_TN_TILES)   // 512
#define G2_TN_TILES (OUT_F / TN)                   // 32
#define G2_TILES    ((M_TOK / TM) * G2_TN_TILES)   // 2048
#define MBLKS       (M_TOK / TM)                   // 64

__device__ __half g_W1[(size_t)RANK * IN_F];     // 8 MB  (Vh - 128)
__device__ __half g_W2[(size_t)OUT_F * RANK];    // 8 MB  (U - 128)
__device__ __half g_H [(size_t)M_TOK * RANK];    // 16 MB (h * hscale)
__device__ float  g_hscale[RANK];
__device__ int    g_flags[MBLKS];

// ------------------------- merged prep kernel ------------------------------
#define NW1_CH  ((size_t)RANK * IN_F / 4)
#define NW2_CH  ((size_t)OUT_F * RANK / 4)

__global__ void prep_all(const int* __restrict__ Vh_data, const float* __restrict__ Vh_zp,
                         const int* __restrict__ U_data,  const float* __restrict__ U_zp,
                         const int* __restrict__ S_data,  const float* __restrict__ S_scale,
                         const float* __restrict__ S_zp,  const float* __restrict__ Vh_scale) {
    size_t g = (size_t)blockIdx.x * blockDim.x + threadIdx.x;
    if (g < NW1_CH) {
        size_t i = g * 4;
        float z = *Vh_zp;
        int4 d = *(const int4*)(Vh_data + i);
        *(__half2*)(g_W1 + i)     = __floats2half2_rn((float)d.x - z, (float)d.y - z);
        *(__half2*)(g_W1 + i + 2) = __floats2half2_rn((float)d.z - z, (float)d.w - z);
    } else if (g < NW1_CH + NW2_CH) {
        size_t i = (g - NW1_CH) * 4;
        float z = *U_zp;
        int4 d = *(const int4*)(U_data + i);
        *(__half2*)(g_W2 + i)     = __floats2half2_rn((float)d.x - z, (float)d.y - z);
        *(__half2*)(g_W2 + i + 2) = __floats2half2_rn((float)d.z - z, (float)d.w - z);
    } else if (g < NW1_CH + NW2_CH + RANK) {
        int r = (int)(g - NW1_CH - NW2_CH);
        g_hscale[r] = Vh_scale[0] * S_scale[0] * ((float)S_data[r] - S_zp[0]);
    } else if (g < NW1_CH + NW2_CH + RANK + MBLKS) {
        g_flags[g - NW1_CH - NW2_CH - RANK] = 0;
    }
}

// ---------------------------- PTX helpers ----------------------------------
__device__ __forceinline__ void cp_async16(uint32_t saddr, const void* gp) {
    asm volatile("cp.async.cg.shared.global [%0], [%1], 16;\n" :: "r"(saddr), "l"(gp));
}
__device__ __forceinline__ void cp_commit() { asm volatile("cp.async.commit_group;\n"); }
template<int N> __device__ __forceinline__ void cp_wait() {
    asm volatile("cp.async.wait_group %0;\n" :: "n"(N));
}
__device__ __forceinline__ void mma16816(float* d, const uint32_t* a, const uint32_t* b) {
    asm volatile(
        "mma.sync.aligned.m16n8k16.row.col.f32.f16.f16.f32 "
        "{%0,%1,%2,%3}, {%4,%5,%6,%7}, {%8,%9}, {%0,%1,%2,%3};\n"
        : "+f"(d[0]), "+f"(d[1]), "+f"(d[2]), "+f"(d[3])
        : "r"(a[0]), "r"(a[1]), "r"(a[2]), "r"(a[3]), "r"(b[0]), "r"(b[1]));
}
__device__ __forceinline__ uint32_t pack_f16x2(float x, float y) {
    uint32_t r;
    asm("cvt.rn.f16x2.f32 %0, %1, %2;" : "=r"(r) : "f"(y), "f"(x));
    return r;
}
__device__ __forceinline__ int ld_acquire_gpu(const int* p) {
    int v;
    asm volatile("ld.acquire.gpu.s32 %0, [%1];" : "=r"(v) : "l"(p) : "memory");
    return v;
}

// ----------------------------- GEMM body -----------------------------------
#define BKH     64
#define SROW    72
#define B_BYTES (TN * SROW * 2)             // 18432
#define A_BYTES_16 (TM * SROW * 2)          // 18432
#define A_BYTES_32 (TM * SROW * 4)          // 36864
#define SMEM_USE 110592                     // both paths: exactly this

// MODE 0 (GEMM1): AFP32=1, NSTG=2.  MODE 1 (GEMM2): AFP32=0, NSTG=3.
// 8 warps, warp grid 4x2: warp tile 32 (m) x 64 (n).
template<int MODE, int AFP32, int NSTG>
__device__ __forceinline__ void
gemm_body(const void* __restrict__ Av, const __half* __restrict__ B,
          void* __restrict__ Cv, int N, int K,
          const float* __restrict__ vec, float us,
          int m0, int n0, char* smc) {
    const uint32_t smem_base = (uint32_t)__cvta_generic_to_shared(smc);
    constexpr int A_BYTES = AFP32 ? A_BYTES_32 : A_BYTES_16;
    constexpr int STG_BYTES = A_BYTES + B_BYTES;

    const int tid  = threadIdx.x;
    const int warp = tid >> 5;
    const int lane = tid & 31;
    const int wm = (warp >> 1) * 32;        // 0/32/64/96
    const int wn = (warp & 1) * 64;         // 0/64
    const int g  = lane >> 2;
    const int tg = lane & 3;
    const int KT = K / BKH;

    auto load_stage = [&](int kt, int s) {
        const uint32_t tA = smem_base + (uint32_t)(s * STG_BYTES);
        const uint32_t tB = tA + A_BYTES;
        if (AFP32) {
            const float* gA = (const float*)Av + (size_t)m0 * K + (size_t)kt * BKH;
#pragma unroll
            for (int r = 0; r < 8; r++) {           // 2048 chunks: 128 rows x 16
                int i = tid + r * 256;
                int row = i >> 4, c = i & 15;
                cp_async16(tA + (uint32_t)(row * SROW + c * 4) * 4,
                           gA + (size_t)row * K + c * 4);
            }
        } else {
            const __half* gA = (const __half*)Av + (size_t)m0 * K + (size_t)kt * BKH;
#pragma unroll
            for (int r = 0; r < 4; r++) {           // 1024 chunks: 128 rows x 8
                int i = tid + r * 256;
                int row = i >> 3, c = i & 7;
                cp_async16(tA + (uint32_t)(row * SROW + c * 8) * 2,
                           gA + (size_t)row * K + c * 8);
            }
        }
        const __half* gB = B + (size_t)n0 * K + (size_t)kt * BKH;
#pragma unroll
        for (int r = 0; r < 4; r++) {               // 1024 chunks: 128 rows x 8
            int i = tid + r * 256;
            int row = i >> 3, c = i & 7;
            cp_async16(tB + (uint32_t)(row * SROW + c * 8) * 2,
                       gB + (size_t)row * K + c * 8);
        }
    };

#pragma unroll
    for (int s = 0; s < NSTG - 1; s++) { load_stage(s, s); cp_commit(); }

    float d[2][8][4];
#pragma unroll
    for (int i = 0; i < 2; i++)
#pragma unroll
        for (int j = 0; j < 8; j++)
#pragma unroll
            for (int c = 0; c < 4; c++) d[i][j][c] = 0.f;

    for (int kt = 0; kt < KT; kt++) {
        cp_wait<NSTG - 2>();
        __syncthreads();

        const int nk = kt + NSTG - 1;
        if (nk < KT) load_stage(nk, nk % NSTG);
        cp_commit();

        const char* stg = smc + (kt % NSTG) * STG_BYTES;
        const __half* sB = (const __half*)(stg + A_BYTES);

#pragma unroll
        for (int ks = 0; ks < 4; ks++) {
            const int ko = ks * 16;
            uint32_t a[2][4], b[8][2];
            if (AFP32) {
                const float* sA = (const float*)stg;
#pragma unroll
                for (int i = 0; i < 2; i++) {
                    const float* p = sA + (wm + i * 16 + g) * SROW + ko + tg * 2;
                    float2 v0 = *(const float2*)p;
                    float2 v1 = *(const float2*)(p + 8 * SROW);
                    float2 v2 = *(const float2*)(p + 8);
                    float2 v3 = *(const float2*)(p + 8 * SROW + 8);
                    a[i][0] = pack_f16x2(v0.x, v0.y);
                    a[i][1] = pack_f16x2(v1.x, v1.y);
                    a[i][2] = pack_f16x2(v2.x, v2.y);
                    a[i][3] = pack_f16x2(v3.x, v3.y);
                }
            } else {
                const __half* sA = (const __half*)stg;
#pragma unroll
                for (int i = 0; i < 2; i++) {
                    const __half* p = sA + (wm + i * 16 + g) * SROW + ko + tg * 2;
                    a[i][0] = *(const uint32_t*)p;
                    a[i][1] = *(const uint32_t*)(p + 8 * SROW);
                    a[i][2] = *(const uint32_t*)(p + 8);
                    a[i][3] = *(const uint32_t*)(p + 8 * SROW + 8);
                }
            }
#pragma unroll
            for (int j = 0; j < 8; j++) {
                const __half* p = sB + (wn + j * 8 + g) * SROW + ko + tg * 2;
                b[j][0] = *(const uint32_t*)p;
                b[j][1] = *(const uint32_t*)(p + 8);
            }
#pragma unroll
            for (int i = 0; i < 2; i++)
#pragma unroll
                for (int j = 0; j < 8; j++)
                    mma16816(d[i][j], a[i], b[j]);
        }
    }

    if (MODE == 0) {
        __half* C = (__half*)Cv;
#pragma unroll
        for (int i = 0; i < 2; i++) {
#pragma unroll
            for (int j = 0; j < 8; j++) {
                int col = n0 + wn + j * 8 + tg * 2;
                float s0 = vec[col], s1 = vec[col + 1];
                int r0 = m0 + wm + i * 16 + g;
                *(__half2*)(C + (size_t)r0 * N + col) =
                    __floats2half2_rn(d[i][j][0] * s0, d[i][j][1] * s1);
                *(__half2*)(C + (size_t)(r0 + 8) * N + col) =
                    __floats2half2_rn(d[i][j][2] * s0, d[i][j][3] * s1);
            }
        }
    } else {
        float* C = (float*)Cv;
#pragma unroll
        for (int i = 0; i < 2; i++) {
#pragma unroll
            for (int j = 0; j < 8; j++) {
                int col = n0 + wn + j * 8 + tg * 2;
                float b0 = vec[col], b1 = vec[col + 1];
                int r0 = m0 + wm + i * 16 + g;
                *(float2*)(C + (size_t)r0 * N + col) =
                    make_float2(d[i][j][0] * us + b0, d[i][j][1] * us + b1);
                *(float2*)(C + (size_t)(r0 + 8) * N + col) =
                    make_float2(d[i][j][2] * us + b0, d[i][j][3] * us + b1);
            }
        }
    }
}

// --------------------------- fused GEMM kernel ------------------------------
// bids [0, 512): GEMM1 tiles (m-major). bids [512, 2560): GEMM2 tiles (m-major).
__global__ void __launch_bounds__(256, 2)
fused_gemm(const float* __restrict__ x, float* __restrict__ out,
           const float* __restrict__ uscale, const float* __restrict__ bias) {
    extern __shared__ char smc[];
    const int bid = blockIdx.x;

    if (bid < G1_TILES) {
        const int mb = bid >> 3;             // 8 n-tiles per m-block
        const int n0 = (bid & 7) * TN;
        gemm_body<0, 1, 2>(x, g_W1, g_H, RANK, IN_F, g_hscale, 0.f,
                           mb * TM, n0, smc);
        __threadfence();
        __syncthreads();
        if (threadIdx.x == 0) atomicAdd(&g_flags[mb], 1);
    } else {
        const int b2 = bid - G1_TILES;
        const int mb = b2 >> 5;              // 32 n-tiles per m-block
        const int n0 = (b2 & 31) * TN;
        if (threadIdx.x == 0) {
            while (ld_acquire_gpu(&g_flags[mb]) < G1_TN_TILES) { }
        }
        __syncthreads();
        const float us = __ldg(uscale);
        gemm_body<1, 0, 3>(g_H, g_W2, out, OUT_F, RANK, bias, us,
                           mb * TM, n0, smc);
    }
}

// ------------------------------ launch -------------------------------------
extern "C" void kernel_launch(void* const* d_in, const int* in_sizes, int n_in,
                              void* d_out, int out_size) {
    const float* x        = (const float*)d_in[0];
    const int*   U_data   = (const int*)  d_in[1];
    const float* U_scale  = (const float*)d_in[2];
    const float* U_zp     = (const float*)d_in[3];
    const int*   S_data   = (const int*)  d_in[4];
    const float* S_scale  = (const float*)d_in[5];
    const float* S_zp     = (const float*)d_in[6];
    const int*   Vh_data  = (const int*)  d_in[7];
    const float* Vh_scale = (const float*)d_in[8];
    const float* Vh_zp    = (const float*)d_in[9];
    const float* bias     = (const float*)d_in[10];
    float* out = (float*)d_out;
    (void)in_sizes; (void)n_in; (void)out_size;

    cudaFuncSetAttribute(fused_gemm, cudaFuncAttributeMaxDynamicSharedMemorySize,
                         SMEM_USE);

    // prep: W1, W2, hscale, flag reset
    {
        size_t total = NW1_CH + NW2_CH + RANK + MBLKS;
        prep_all<<<(unsigned)((total + 255) / 256), 256>>>(
            Vh_data, Vh_zp, U_data, U_zp, S_data, S_scale, S_zp, Vh_scale);
    }
    // fused GEMM1 + GEMM2 (flag-based cross-tile dependency)
    fused_gemm<<<G1_TILES + G2_TILES, 256, SMEM_USE>>>(x, out, U_scale, bias);
}

// round 10
// speedup vs baseline: 1.0696x; 1.0696x over previous
#include <cuda_runtime.h>
#include <cuda_fp16.h>
#include <cstdint>

// ---------------------------------------------------------------------------
// CompressedLinear: y = ((x @ Vh^T) * S) @ U^T + bias
// mma.sync fp16 path. R9 falsified "more warps": limiter is LDS/issue in the
// frag-load path. This round: R8 config (128x128 tile, 4 warps @ 64x64,
// 2 CTAs/SM, smem 110592B) + ldmatrix.x4 fragment loads (4x fewer LDS instr).
// GEMM1 A stays fp32-staged scalar+pack; all fp16 frags use LDSM.
// ---------------------------------------------------------------------------

#define M_TOK   8192
#define IN_F    4096
#define OUT_F   4096
#define RANK    1024

#define TM      128
#define TN      128
#define G1_TN_TILES (RANK / TN)                    // 8
#define G1_TILES    ((M_TOK / TM) * G1_TN_TILES)   // 512
#define G2_TN_TILES (OUT_F / TN)                   // 32
#define G2_TILES    ((M_TOK / TM) * G2_TN_TILES)   // 2048
#define MBLKS       (M_TOK / TM)                   // 64

__device__ __half g_W1[(size_t)RANK * IN_F];     // 8 MB  (Vh - 128)
__device__ __half g_W2[(size_t)OUT_F * RANK];    // 8 MB  (U - 128)
__device__ __half g_H [(size_t)M_TOK * RANK];    // 16 MB (h * hscale)
__device__ float  g_hscale[RANK];
__device__ int    g_flags[MBLKS];

// ------------------------- merged prep kernel ------------------------------
#define NW1_CH  ((size_t)RANK * IN_F / 4)
#define NW2_CH  ((size_t)OUT_F * RANK / 4)

__global__ void prep_all(const int* __restrict__ Vh_data, const float* __restrict__ Vh_zp,
                         const int* __restrict__ U_data,  const float* __restrict__ U_zp,
                         const int* __restrict__ S_data,  const float* __restrict__ S_scale,
                         const float* __restrict__ S_zp,  const float* __restrict__ Vh_scale) {
    size_t g = (size_t)blockIdx.x * blockDim.x + threadIdx.x;
    if (g < NW1_CH) {
        size_t i = g * 4;
        float z = *Vh_zp;
        int4 d = *(const int4*)(Vh_data + i);
        *(__half2*)(g_W1 + i)     = __floats2half2_rn((float)d.x - z, (float)d.y - z);
        *(__half2*)(g_W1 + i + 2) = __floats2half2_rn((float)d.z - z, (float)d.w - z);
    } else if (g < NW1_CH + NW2_CH) {
        size_t i = (g - NW1_CH) * 4;
        float z = *U_zp;
        int4 d = *(const int4*)(U_data + i);
        *(__half2*)(g_W2 + i)     = __floats2half2_rn((float)d.x - z, (float)d.y - z);
        *(__half2*)(g_W2 + i + 2) = __floats2half2_rn((float)d.z - z, (float)d.w - z);
    } else if (g < NW1_CH + NW2_CH + RANK) {
        int r = (int)(g - NW1_CH - NW2_CH);
        g_hscale[r] = Vh_scale[0] * S_scale[0] * ((float)S_data[r] - S_zp[0]);
    } else if (g < NW1_CH + NW2_CH + RANK + MBLKS) {
        g_flags[g - NW1_CH - NW2_CH - RANK] = 0;
    }
}

// ---------------------------- PTX helpers ----------------------------------
__device__ __forceinline__ void cp_async16(uint32_t saddr, const void* gp) {
    asm volatile("cp.async.cg.shared.global [%0], [%1], 16;\n" :: "r"(saddr), "l"(gp));
}
__device__ __forceinline__ void cp_commit() { asm volatile("cp.async.commit_group;\n"); }
template<int N> __device__ __forceinline__ void cp_wait() {
    asm volatile("cp.async.wait_group %0;\n" :: "n"(N));
}
__device__ __forceinline__ void mma16816(float* d, const uint32_t* a, const uint32_t* b) {
    asm volatile(
        "mma.sync.aligned.m16n8k16.row.col.f32.f16.f16.f32 "
        "{%0,%1,%2,%3}, {%4,%5,%6,%7}, {%8,%9}, {%0,%1,%2,%3};\n"
        : "+f"(d[0]), "+f"(d[1]), "+f"(d[2]), "+f"(d[3])
        : "r"(a[0]), "r"(a[1]), "r"(a[2]), "r"(a[3]), "r"(b[0]), "r"(b[1]));
}
__device__ __forceinline__ uint32_t pack_f16x2(float x, float y) {
    uint32_t r;
    asm("cvt.rn.f16x2.f32 %0, %1, %2;" : "=r"(r) : "f"(y), "f"(x));
    return r;
}
__device__ __forceinline__ int ld_acquire_gpu(const int* p) {
    int v;
    asm volatile("ld.acquire.gpu.s32 %0, [%1];" : "=r"(v) : "l"(p) : "memory");
    return v;
}
__device__ __forceinline__ void ldsm_x4(uint32_t& r0, uint32_t& r1,
                                        uint32_t& r2, uint32_t& r3, uint32_t saddr) {
    asm volatile("ldmatrix.sync.aligned.m8n8.x4.shared.b16 {%0,%1,%2,%3}, [%4];"
                 : "=r"(r0), "=r"(r1), "=r"(r2), "=r"(r3) : "r"(saddr));
}

// ----------------------------- GEMM body -----------------------------------
#define BKH     64
#define SROW    72
#define B_BYTES (TN * SROW * 2)             // 18432
#define A_BYTES_16 (TM * SROW * 2)          // 18432
#define A_BYTES_32 (TM * SROW * 4)          // 36864
#define SMEM_USE 110592                     // both paths: exactly this

// MODE 0 (GEMM1): AFP32=1, NSTG=2.  MODE 1 (GEMM2): AFP32=0, NSTG=3.
// 4 warps, warp grid 2x2: warp tile 64x64.
template<int MODE, int AFP32, int NSTG>
__device__ __forceinline__ void
gemm_body(const void* __restrict__ Av, const __half* __restrict__ B,
          void* __restrict__ Cv, int N, int K,
          const float* __restrict__ vec, float us,
          int m0, int n0, char* smc) {
    const uint32_t smem_base = (uint32_t)__cvta_generic_to_shared(smc);
    constexpr int A_BYTES = AFP32 ? A_BYTES_32 : A_BYTES_16;
    constexpr int STG_BYTES = A_BYTES + B_BYTES;

    const int tid  = threadIdx.x;
    const int warp = tid >> 5;
    const int lane = tid & 31;
    const int wm = (warp >> 1) * 64;        // 0 / 64
    const int wn = (warp & 1) * 64;         // 0 / 64
    const int g  = lane >> 2;
    const int tg = lane & 3;
    const int KT = K / BKH;

    // LDSM lane-address components (halfs)
    const int a_row = (lane & 15);               // row within m16 tile
    const int a_col = (lane >> 4) << 3;          // 0 or 8 (k offset)
    const int b_row = ((lane >> 4) << 3) + (lane & 7);  // row within n16 pair
    const int b_col = ((lane >> 3) & 1) << 3;    // 0 or 8 (k offset)

    auto load_stage = [&](int kt, int s) {
        const uint32_t tA = smem_base + (uint32_t)(s * STG_BYTES);
        const uint32_t tB = tA + A_BYTES;
        if (AFP32) {
            const float* gA = (const float*)Av + (size_t)m0 * K + (size_t)kt * BKH;
#pragma unroll
            for (int r = 0; r < 16; r++) {          // 2048 chunks: 128 rows x 16
                int i = tid + r * 128;
                int row = i >> 4, c = i & 15;
                cp_async16(tA + (uint32_t)(row * SROW + c * 4) * 4,
                           gA + (size_t)row * K + c * 4);
            }
        } else {
            const __half* gA = (const __half*)Av + (size_t)m0 * K + (size_t)kt * BKH;
#pragma unroll
            for (int r = 0; r < 8; r++) {           // 1024 chunks: 128 rows x 8
                int i = tid + r * 128;
                int row = i >> 3, c = i & 7;
                cp_async16(tA + (uint32_t)(row * SROW + c * 8) * 2,
                           gA + (size_t)row * K + c * 8);
            }
        }
        const __half* gB = B + (size_t)n0 * K + (size_t)kt * BKH;
#pragma unroll
        for (int r = 0; r < 8; r++) {               // 1024 chunks: 128 rows x 8
            int i = tid + r * 128;
            int row = i >> 3, c = i & 7;
            cp_async16(tB + (uint32_t)(row * SROW + c * 8) * 2,
                       gB + (size_t)row * K + c * 8);
        }
    };

#pragma unroll
    for (int s = 0; s < NSTG - 1; s++) { load_stage(s, s); cp_commit(); }

    float d[4][8][4];
#pragma unroll
    for (int i = 0; i < 4; i++)
#pragma unroll
        for (int j = 0; j < 8; j++)
#pragma unroll
            for (int c = 0; c < 4; c++) d[i][j][c] = 0.f;

    for (int kt = 0; kt < KT; kt++) {
        cp_wait<NSTG - 2>();
        __syncthreads();

        const int nk = kt + NSTG - 1;
        if (nk < KT) load_stage(nk, nk % NSTG);
        cp_commit();

        const uint32_t sA_u = smem_base + (uint32_t)((kt % NSTG) * STG_BYTES);
        const uint32_t sB_u = sA_u + A_BYTES;
        const char* stg = smc + (kt % NSTG) * STG_BYTES;

#pragma unroll
        for (int ks = 0; ks < 4; ks++) {
            const int ko = ks * 16;
            uint32_t a[4][4], b[8][2];
            if (AFP32) {
                const float* sA = (const float*)stg;
#pragma unroll
                for (int i = 0; i < 4; i++) {
                    const float* p = sA + (wm + i * 16 + g) * SROW + ko + tg * 2;
                    float2 v0 = *(const float2*)p;
                    float2 v1 = *(const float2*)(p + 8 * SROW);
                    float2 v2 = *(const float2*)(p + 8);
                    float2 v3 = *(const float2*)(p + 8 * SROW + 8);
                    a[i][0] = pack_f16x2(v0.x, v0.y);
                    a[i][1] = pack_f16x2(v1.x, v1.y);
                    a[i][2] = pack_f16x2(v2.x, v2.y);
                    a[i][3] = pack_f16x2(v3.x, v3.y);
                }
            } else {
                // A frags: 4x ldmatrix.x4 (m16k16 each)
#pragma unroll
                for (int i = 0; i < 4; i++) {
                    uint32_t addr = sA_u +
                        (uint32_t)((wm + i * 16 + a_row) * SROW + ko + a_col) * 2;
                    ldsm_x4(a[i][0], a[i][1], a[i][2], a[i][3], addr);
                }
            }
            // B frags: 4x ldmatrix.x4 (two n8k16 tiles each)
#pragma unroll
            for (int jj = 0; jj < 4; jj++) {
                uint32_t addr = sB_u +
                    (uint32_t)((wn + jj * 16 + b_row) * SROW + ko + b_col) * 2;
                ldsm_x4(b[2 * jj][0], b[2 * jj][1],
                        b[2 * jj + 1][0], b[2 * jj + 1][1], addr);
            }
#pragma unroll
            for (int i = 0; i < 4; i++)
#pragma unroll
                for (int j = 0; j < 8; j++)
                    mma16816(d[i][j], a[i], b[j]);
        }
    }

    if (MODE == 0) {
        __half* C = (__half*)Cv;
#pragma unroll
        for (int i = 0; i < 4; i++) {
#pragma unroll
            for (int j = 0; j < 8; j++) {
                int col = n0 + wn + j * 8 + tg * 2;
                float s0 = vec[col], s1 = vec[col + 1];
                int r0 = m0 + wm + i * 16 + g;
                *(__half2*)(C + (size_t)r0 * N + col) =
                    __floats2half2_rn(d[i][j][0] * s0, d[i][j][1] * s1);
                *(__half2*)(C + (size_t)(r0 + 8) * N + col) =
                    __floats2half2_rn(d[i][j][2] * s0, d[i][j][3] * s1);
            }
        }
    } else {
        float* C = (float*)Cv;
#pragma unroll
        for (int i = 0; i < 4; i++) {
#pragma unroll
            for (int j = 0; j < 8; j++) {
                int col = n0 + wn + j * 8 + tg * 2;
                float b0 = vec[col], b1 = vec[col + 1];
                int r0 = m0 + wm + i * 16 + g;
                *(float2*)(C + (size_t)r0 * N + col) =
                    make_float2(d[i][j][0] * us + b0, d[i][j][1] * us + b1);
                *(float2*)(C + (size_t)(r0 + 8) * N + col) =
                    make_float2(d[i][j][2] * us + b0, d[i][j][3] * us + b1);
            }
        }
    }
}

// --------------------------- fused GEMM kernel ------------------------------
// bids [0, 512): GEMM1 tiles (m-major). bids [512, 2560): GEMM2 tiles (m-major).
__global__ void __launch_bounds__(128, 2)
fused_gemm(const float* __restrict__ x, float* __restrict__ out,
           const float* __restrict__ uscale, const float* __restrict__ bias) {
    extern __shared__ char smc[];
    const int bid = blockIdx.x;

    if (bid < G1_TILES) {
        const int mb = bid >> 3;             // 8 n-tiles per m-block
        const int n0 = (bid & 7) * TN;
        gemm_body<0, 1, 2>(x, g_W1, g_H, RANK, IN_F, g_hscale, 0.f,
                           mb * TM, n0, smc);
        __threadfence();
        __syncthreads();
        if (threadIdx.x == 0) atomicAdd(&g_flags[mb], 1);
    } else {
        const int b2 = bid - G1_TILES;
        const int mb = b2 >> 5;              // 32 n-tiles per m-block
        const int n0 = (b2 & 31) * TN;
        if (threadIdx.x == 0) {
            while (ld_acquire_gpu(&g_flags[mb]) < G1_TN_TILES) { }
        }
        __syncthreads();
        const float us = __ldg(uscale);
        gemm_body<1, 0, 3>(g_H, g_W2, out, OUT_F, RANK, bias, us,
                           mb * TM, n0, smc);
    }
}

// ------------------------------ launch -------------------------------------
extern "C" void kernel_launch(void* const* d_in, const int* in_sizes, int n_in,
                              void* d_out, int out_size) {
    const float* x        = (const float*)d_in[0];
    const int*   U_data   = (const int*)  d_in[1];
    const float* U_scale  = (const float*)d_in[2];
    const float* U_zp     = (const float*)d_in[3];
    const int*   S_data   = (const int*)  d_in[4];
    const float* S_scale  = (const float*)d_in[5];
    const float* S_zp     = (const float*)d_in[6];
    const int*   Vh_data  = (const int*)  d_in[7];
    const float* Vh_scale = (const float*)d_in[8];
    const float* Vh_zp    = (const float*)d_in[9];
    const float* bias     = (const float*)d_in[10];
    float* out = (float*)d_out;
    (void)in_sizes; (void)n_in; (void)out_size;

    cudaFuncSetAttribute(fused_gemm, cudaFuncAttributeMaxDynamicSharedMemorySize,
                         SMEM_USE);

    // prep: W1, W2, hscale, flag reset
    {
        size_t total = NW1_CH + NW2_CH + RANK + MBLKS;
        prep_all<<<(unsigned)((total + 255) / 256), 256>>>(
            Vh_data, Vh_zp, U_data, U_zp, S_data, S_scale, S_zp, Vh_scale);
    }
    // fused GEMM1 + GEMM2 (flag-based cross-tile dependency)
    fused_gemm<<<G1_TILES + G2_TILES, 128, SMEM_USE>>>(x, out, U_scale, bias);
}

// round 11
// speedup vs baseline: 1.0910x; 1.0200x over previous
#include <cuda_runtime.h>
#include <cuda_fp16.h>
#include <cstdint>

// ---------------------------------------------------------------------------
// CompressedLinear: y = ((x @ Vh^T) * S) @ U^T + bias
// mma.sync fp16 path. R10: tensor=57%; GEMM1 still had scalar fp32 A-loads
// (bank conflicts) and NSTG=2 full-drain pipeline. This round: x converted to
// fp16 in prep (parallel), unified all-fp16 GEMM body, all ldmatrix.x4 frag
// loads, NSTG=3 both GEMMs, 2 CTAs/SM, 64x64 warp tiles. Fused launch+flags.
// ---------------------------------------------------------------------------

#define M_TOK   8192
#define IN_F    4096
#define OUT_F   4096
#define RANK    1024

#define TM      128
#define TN      128
#define G1_TN_TILES (RANK / TN)                    // 8
#define G1_TILES    ((M_TOK / TM) * G1_TN_TILES)   // 512
#define G2_TN_TILES (OUT_F / TN)                   // 32
#define G2_TILES    ((M_TOK / TM) * G2_TN_TILES)   // 2048
#define MBLKS       (M_TOK / TM)                   // 64

__device__ __half g_x16[(size_t)M_TOK * IN_F];   // 64 MB (fp16 x)
__device__ __half g_W1[(size_t)RANK * IN_F];     // 8 MB  (Vh - 128)
__device__ __half g_W2[(size_t)OUT_F * RANK];    // 8 MB  (U - 128)
__device__ __half g_H [(size_t)M_TOK * RANK];    // 16 MB (h * hscale)
__device__ float  g_hscale[RANK];
__device__ int    g_flags[MBLKS];

// ------------------------- merged prep kernel ------------------------------
#define NX_CH   ((size_t)M_TOK * IN_F / 4)       // 8,388,608 chunks
#define NW1_CH  ((size_t)RANK * IN_F / 4)        // 1,048,576
#define NW2_CH  ((size_t)OUT_F * RANK / 4)       // 1,048,576

__global__ void prep_all(const float* __restrict__ x,
                         const int* __restrict__ Vh_data, const float* __restrict__ Vh_zp,
                         const int* __restrict__ U_data,  const float* __restrict__ U_zp,
                         const int* __restrict__ S_data,  const float* __restrict__ S_scale,
                         const float* __restrict__ S_zp,  const float* __restrict__ Vh_scale) {
    size_t g = (size_t)blockIdx.x * blockDim.x + threadIdx.x;
    if (g < NX_CH) {
        size_t i = g * 4;
        float4 v = *(const float4*)(x + i);
        *(__half2*)(g_x16 + i)     = __floats2half2_rn(v.x, v.y);
        *(__half2*)(g_x16 + i + 2) = __floats2half2_rn(v.z, v.w);
    } else if (g < NX_CH + NW1_CH) {
        size_t i = (g - NX_CH) * 4;
        float z = *Vh_zp;
        int4 d = *(const int4*)(Vh_data + i);
        *(__half2*)(g_W1 + i)     = __floats2half2_rn((float)d.x - z, (float)d.y - z);
        *(__half2*)(g_W1 + i + 2) = __floats2half2_rn((float)d.z - z, (float)d.w - z);
    } else if (g < NX_CH + NW1_CH + NW2_CH) {
        size_t i = (g - NX_CH - NW1_CH) * 4;
        float z = *U_zp;
        int4 d = *(const int4*)(U_data + i);
        *(__half2*)(g_W2 + i)     = __floats2half2_rn((float)d.x - z, (float)d.y - z);
        *(__half2*)(g_W2 + i + 2) = __floats2half2_rn((float)d.z - z, (float)d.w - z);
    } else if (g < NX_CH + NW1_CH + NW2_CH + RANK) {
        int r = (int)(g - NX_CH - NW1_CH - NW2_CH);
        g_hscale[r] = Vh_scale[0] * S_scale[0] * ((float)S_data[r] - S_zp[0]);
    } else if (g < NX_CH + NW1_CH + NW2_CH + RANK + MBLKS) {
        g_flags[g - NX_CH - NW1_CH - NW2_CH - RANK] = 0;
    }
}

// ---------------------------- PTX helpers ----------------------------------
__device__ __forceinline__ void cp_async16(uint32_t saddr, const void* gp) {
    asm volatile("cp.async.cg.shared.global [%0], [%1], 16;\n" :: "r"(saddr), "l"(gp));
}
__device__ __forceinline__ void cp_commit() { asm volatile("cp.async.commit_group;\n"); }
template<int N> __device__ __forceinline__ void cp_wait() {
    asm volatile("cp.async.wait_group %0;\n" :: "n"(N));
}
__device__ __forceinline__ void mma16816(float* d, const uint32_t* a, const uint32_t* b) {
    asm volatile(
        "mma.sync.aligned.m16n8k16.row.col.f32.f16.f16.f32 "
        "{%0,%1,%2,%3}, {%4,%5,%6,%7}, {%8,%9}, {%0,%1,%2,%3};\n"
        : "+f"(d[0]), "+f"(d[1]), "+f"(d[2]), "+f"(d[3])
        : "r"(a[0]), "r"(a[1]), "r"(a[2]), "r"(a[3]), "r"(b[0]), "r"(b[1]));
}
__device__ __forceinline__ int ld_acquire_gpu(const int* p) {
    int v;
    asm volatile("ld.acquire.gpu.s32 %0, [%1];" : "=r"(v) : "l"(p) : "memory");
    return v;
}
__device__ __forceinline__ void ldsm_x4(uint32_t& r0, uint32_t& r1,
                                        uint32_t& r2, uint32_t& r3, uint32_t saddr) {
    asm volatile("ldmatrix.sync.aligned.m8n8.x4.shared.b16 {%0,%1,%2,%3}, [%4];"
                 : "=r"(r0), "=r"(r1), "=r"(r2), "=r"(r3) : "r"(saddr));
}

// ----------------------------- GEMM body -----------------------------------
#define BKH     64
#define NSTG    3
#define SROW    72
#define A_BYTES (TM * SROW * 2)             // 18432
#define B_BYTES (TN * SROW * 2)             // 18432
#define STG_BYTES (A_BYTES + B_BYTES)       // 36864
#define SMEM_USE (NSTG * STG_BYTES)         // 110592

// MODE 0 (GEMM1): C half, *= vec[col].  MODE 1 (GEMM2): C float, *us + vec.
// 4 warps, warp grid 2x2: warp tile 64x64. All fp16, all LDSM.
template<int MODE>
__device__ __forceinline__ void
gemm_body(const __half* __restrict__ A, const __half* __restrict__ B,
          void* __restrict__ Cv, int N, int K,
          const float* __restrict__ vec, float us,
          int m0, int n0, char* smc) {
    const uint32_t smem_base = (uint32_t)__cvta_generic_to_shared(smc);

    const int tid  = threadIdx.x;
    const int warp = tid >> 5;
    const int lane = tid & 31;
    const int wm = (warp >> 1) * 64;        // 0 / 64
    const int wn = (warp & 1) * 64;         // 0 / 64
    const int g  = lane >> 2;
    const int tg = lane & 3;
    const int KT = K / BKH;

    // LDSM lane-address components (halfs)
    const int a_row = (lane & 15);
    const int a_col = (lane >> 4) << 3;
    const int b_row = ((lane >> 4) << 3) + (lane & 7);
    const int b_col = ((lane >> 3) & 1) << 3;

    auto load_stage = [&](int kt, int s) {
        const uint32_t tA = smem_base + (uint32_t)(s * STG_BYTES);
        const uint32_t tB = tA + A_BYTES;
        const __half* gA = A + (size_t)m0 * K + (size_t)kt * BKH;
        const __half* gB = B + (size_t)n0 * K + (size_t)kt * BKH;
#pragma unroll
        for (int r = 0; r < 8; r++) {               // 1024 chunks: 128 rows x 8
            int i = tid + r * 128;
            int row = i >> 3, c = i & 7;
            cp_async16(tA + (uint32_t)(row * SROW + c * 8) * 2,
                       gA + (size_t)row * K + c * 8);
        }
#pragma unroll
        for (int r = 0; r < 8; r++) {
            int i = tid + r * 128;
            int row = i >> 3, c = i & 7;
            cp_async16(tB + (uint32_t)(row * SROW + c * 8) * 2,
                       gB + (size_t)row * K + c * 8);
        }
    };

#pragma unroll
    for (int s = 0; s < NSTG - 1; s++) { load_stage(s, s); cp_commit(); }

    float d[4][8][4];
#pragma unroll
    for (int i = 0; i < 4; i++)
#pragma unroll
        for (int j = 0; j < 8; j++)
#pragma unroll
            for (int c = 0; c < 4; c++) d[i][j][c] = 0.f;

    for (int kt = 0; kt < KT; kt++) {
        cp_wait<NSTG - 2>();
        __syncthreads();

        const int nk = kt + NSTG - 1;
        if (nk < KT) load_stage(nk, nk % NSTG);
        cp_commit();

        const uint32_t sA_u = smem_base + (uint32_t)((kt % NSTG) * STG_BYTES);
        const uint32_t sB_u = sA_u + A_BYTES;

#pragma unroll
        for (int ks = 0; ks < 4; ks++) {
            const int ko = ks * 16;
            uint32_t a[4][4], b[8][2];
#pragma unroll
            for (int i = 0; i < 4; i++) {
                uint32_t addr = sA_u +
                    (uint32_t)((wm + i * 16 + a_row) * SROW + ko + a_col) * 2;
                ldsm_x4(a[i][0], a[i][1], a[i][2], a[i][3], addr);
            }
#pragma unroll
            for (int jj = 0; jj < 4; jj++) {
                uint32_t addr = sB_u +
                    (uint32_t)((wn + jj * 16 + b_row) * SROW + ko + b_col) * 2;
                ldsm_x4(b[2 * jj][0], b[2 * jj][1],
                        b[2 * jj + 1][0], b[2 * jj + 1][1], addr);
            }
#pragma unroll
            for (int i = 0; i < 4; i++)
#pragma unroll
                for (int j = 0; j < 8; j++)
                    mma16816(d[i][j], a[i], b[j]);
        }
    }

    if (MODE == 0) {
        __half* C = (__half*)Cv;
#pragma unroll
        for (int i = 0; i < 4; i++) {
#pragma unroll
            for (int j = 0; j < 8; j++) {
                int col = n0 + wn + j * 8 + tg * 2;
                float s0 = vec[col], s1 = vec[col + 1];
                int r0 = m0 + wm + i * 16 + g;
                *(__half2*)(C + (size_t)r0 * N + col) =
                    __floats2half2_rn(d[i][j][0] * s0, d[i][j][1] * s1);
                *(__half2*)(C + (size_t)(r0 + 8) * N + col) =
                    __floats2half2_rn(d[i][j][2] * s0, d[i][j][3] * s1);
            }
        }
    } else {
        float* C = (float*)Cv;
#pragma unroll
        for (int i = 0; i < 4; i++) {
#pragma unroll
            for (int j = 0; j < 8; j++) {
                int col = n0 + wn + j * 8 + tg * 2;
                float b0 = vec[col], b1 = vec[col + 1];
                int r0 = m0 + wm + i * 16 + g;
                *(float2*)(C + (size_t)r0 * N + col) =
                    make_float2(d[i][j][0] * us + b0, d[i][j][1] * us + b1);
                *(float2*)(C + (size_t)(r0 + 8) * N + col) =
                    make_float2(d[i][j][2] * us + b0, d[i][j][3] * us + b1);
            }
        }
    }
}

// --------------------------- fused GEMM kernel ------------------------------
// bids [0, 512): GEMM1 tiles (m-major). bids [512, 2560): GEMM2 tiles (m-major).
__global__ void __launch_bounds__(128, 2)
fused_gemm(float* __restrict__ out,
           const float* __restrict__ uscale, const float* __restrict__ bias) {
    extern __shared__ char smc[];
    const int bid = blockIdx.x;

    if (bid < G1_TILES) {
        const int mb = bid >> 3;             // 8 n-tiles per m-block
        const int n0 = (bid & 7) * TN;
        gemm_body<0>(g_x16, g_W1, g_H, RANK, IN_F, g_hscale, 0.f,
                     mb * TM, n0, smc);
        __threadfence();
        __syncthreads();
        if (threadIdx.x == 0) atomicAdd(&g_flags[mb], 1);
    } else {
        const int b2 = bid - G1_TILES;
        const int mb = b2 >> 5;              // 32 n-tiles per m-block
        const int n0 = (b2 & 31) * TN;
        if (threadIdx.x == 0) {
            while (ld_acquire_gpu(&g_flags[mb]) < G1_TN_TILES) { }
        }
        __syncthreads();
        const float us = __ldg(uscale);
        gemm_body<1>(g_H, g_W2, out, OUT_F, RANK, bias, us,
                     mb * TM, n0, smc);
    }
}

// ------------------------------ launch -------------------------------------
extern "C" void kernel_launch(void* const* d_in, const int* in_sizes, int n_in,
                              void* d_out, int out_size) {
    const float* x        = (const float*)d_in[0];
    const int*   U_data   = (const int*)  d_in[1];
    const float* U_scale  = (const float*)d_in[2];
    const float* U_zp     = (const float*)d_in[3];
    const int*   S_data   = (const int*)  d_in[4];
    const float* S_scale  = (const float*)d_in[5];
    const float* S_zp     = (const float*)d_in[6];
    const int*   Vh_data  = (const int*)  d_in[7];
    const float* Vh_scale = (const float*)d_in[8];
    const float* Vh_zp    = (const float*)d_in[9];
    const float* bias     = (const float*)d_in[10];
    float* out = (float*)d_out;
    (void)in_sizes; (void)n_in; (void)out_size;

    cudaFuncSetAttribute(fused_gemm, cudaFuncAttributeMaxDynamicSharedMemorySize,
                         SMEM_USE);

    // prep: x->fp16, W1, W2, hscale, flag reset (one launch, fully parallel)
    {
        size_t total = NX_CH + NW1_CH + NW2_CH + RANK + MBLKS;
        prep_all<<<(unsigned)((total + 255) / 256), 256>>>(
            x, Vh_data, Vh_zp, U_data, U_zp, S_data, S_scale, S_zp, Vh_scale);
    }
    // fused GEMM1 + GEMM2 (flag-based cross-tile dependency)
    fused_gemm<<<G1_TILES + G2_TILES, 128, SMEM_USE>>>(out, U_scale, bias);
}